// round 3
// baseline (speedup 1.0000x reference)
#include <cuda_runtime.h>
#include <cstddef>

// GaussianIntegral2D — thread-per-pair, CHUNKED warp-local smem staging.
//
// Each thread owns one (b1,b2) pair. The 49 quadrature points are processed
// in two chunks (25 + 24): compute chunk into the warp's smem tile, flush it
// to global with coalesced float2 stores, reuse the tile. Halving the tile
// (vs full 98-float staging) cuts smem/block to ~51KB -> 4 blocks/SM -> 50%
// occupancy (R2 showed occ=22.5% was the binder: nothing saturated).

#define LOG2PI_F 1.8378770664093453f

static constexpr int Q      = 49;
static constexpr int TPB    = 256;
static constexpr int WARPS  = TPB / 32;
static constexpr int C0     = 25;                 // points in chunk 0
static constexpr int C1     = 24;                 // points in chunk 1
static constexpr int ROWF2  = 25;                 // float2 per pair-row in tile
static constexpr int TILEF2 = 32 * ROWF2;         // 800 float2 per warp tile
static constexpr int QD_OFF = WARPS * TILEF2;     // qd table offset (float2 units)
static constexpr size_t SMEM_BYTES = (size_t)QD_OFF * 8 + 64 * 16;

__global__ void __launch_bounds__(TPB)
gauss_integral_kernel(const float* __restrict__ means,   // [P,2]
                      const float* __restrict__ covars,  // [P,4]
                      const float* __restrict__ rots,    // [P,4]
                      const float* __restrict__ trans,   // [P,2]
                      const float* __restrict__ eta,     // [2,Q]
                      const float* __restrict__ wts,     // [Q]
                      float* __restrict__ out_pts,       // [P,Q,2]
                      float* __restrict__ out_int,       // [P]
                      int npair)
{
    extern __shared__ float2 smf2[];
    float4* qd = reinterpret_cast<float4*>(smf2 + QD_OFF);

    const int tid  = threadIdx.x;
    const int lane = tid & 31;
    const int wid  = tid >> 5;

    // Stage quadrature table once per block: {ex, ey, w, 0} per point.
    if (tid < Q)
        qd[tid] = make_float4(eta[tid], eta[Q + tid], wts[tid], 0.0f);
    __syncthreads();

    const int p        = blockIdx.x * TPB + tid;
    const int tilebase = blockIdx.x * TPB + (wid << 5);
    float2* row = smf2 + wid * TILEF2 + lane * ROWF2;

    const float2* tile = smf2 + wid * TILEF2;
    float2* gbase = reinterpret_cast<float2*>(out_pts) + (size_t)tilebase * Q;

    const int rem  = npair - tilebase;
    const int live = rem >= 32 ? 32 : (rem > 0 ? rem : 0);

    // Per-pair parameters (coalesced per-lane vector loads).
    float2 m = make_float2(0.f, 0.f), t = make_float2(0.f, 0.f);
    float4 c = make_float4(1.f, 0.f, 0.f, 1.f), r = c;
    if (p < npair) {
        m = reinterpret_cast<const float2*>(means)[p];
        c = reinterpret_cast<const float4*>(covars)[p];  // c00 c01 c10 c11
        r = reinterpret_cast<const float4*>(rots)[p];
        t = reinterpret_cast<const float2*>(trans)[p];
    }

    const float det  = c.x * c.w - c.y * c.z;
    const float kinv = -0.5f * __frcp_rn(det);
    const float base = fmaf(-0.5f, __logf(det), -LOG2PI_F);
    const float csum = c.y + c.z;

    float acc0 = 0.0f, acc1 = 0.0f;

    // ---- chunk 0: q in [0, 25) ----
    if (p < npair) {
        #pragma unroll 5
        for (int q = 0; q < C0; ++q) {
            const float4 e = qd[q];
            const float px = fmaf(r.x, e.x, fmaf(r.y, e.y, t.x));
            const float py = fmaf(r.z, e.x, fmaf(r.w, e.y, t.y));
            row[q] = make_float2(px, py);
            const float dx = px - m.x, dy = py - m.y;
            const float quad = fmaf(c.w * dx, dx,
                               fmaf(-csum * dx, dy, c.x * dy * dy));
            const float v = __expf(fmaf(kinv, quad, base)) * e.z;
            if (q & 1) acc1 += v; else acc0 += v;
        }
    }
    __syncwarp();

    // flush chunk 0: flat tile (pair-stride 25 f2 == chunk size) -> contiguous
    {
        const int nf2 = live * C0;
        #pragma unroll 4
        for (int j = lane; j < nf2; j += 32) {
            const int pr = j / C0;
            const int e  = j - pr * C0;
            __stcs(gbase + (size_t)pr * Q + e, tile[j]);
        }
    }
    __syncwarp();

    // ---- chunk 1: q in [25, 49) ----
    if (p < npair) {
        #pragma unroll 4
        for (int q = 0; q < C1; ++q) {
            const float4 e = qd[C0 + q];
            const float px = fmaf(r.x, e.x, fmaf(r.y, e.y, t.x));
            const float py = fmaf(r.z, e.x, fmaf(r.w, e.y, t.y));
            row[q] = make_float2(px, py);
            const float dx = px - m.x, dy = py - m.y;
            const float quad = fmaf(c.w * dx, dx,
                               fmaf(-csum * dx, dy, c.x * dy * dy));
            const float v = __expf(fmaf(kinv, quad, base)) * e.z;
            if (q & 1) acc1 += v; else acc0 += v;
        }
        out_int[p] = fminf(fmaxf(acc0 + acc1, 0.0f), 1.0f);
    }
    __syncwarp();

    // flush chunk 1: rows of 24 f2 at smem stride 25, global offset +25
    {
        const int nf2 = live * C1;
        #pragma unroll 4
        for (int j = lane; j < nf2; j += 32) {
            const int pr = j / C1;
            const int e  = j - pr * C1;
            __stcs(gbase + (size_t)pr * Q + C0 + e, tile[pr * ROWF2 + e]);
        }
    }
}

extern "C" void kernel_launch(void* const* d_in, const int* in_sizes, int n_in,
                              void* d_out, int out_size)
{
    const float* means  = (const float*)d_in[0];
    const float* covars = (const float*)d_in[1];
    const float* rots   = (const float*)d_in[2];
    const float* trans  = (const float*)d_in[3];
    const float* eta    = (const float*)d_in[4];
    const float* wts    = (const float*)d_in[5];

    const int npair = in_sizes[0] / 2;

    float* out_pts = (float*)d_out;
    float* out_int = out_pts + (size_t)npair * (size_t)(2 * Q);

    cudaFuncSetAttribute(gauss_integral_kernel,
                         cudaFuncAttributeMaxDynamicSharedMemorySize,
                         (int)SMEM_BYTES);

    const int blocks = (npair + TPB - 1) / TPB;
    gauss_integral_kernel<<<blocks, TPB, SMEM_BYTES>>>(
        means, covars, rots, trans, eta, wts, out_pts, out_int, npair);
}

// round 4
// speedup vs baseline: 1.1177x; 1.1177x over previous
#include <cuda_runtime.h>
#include <cstddef>
#include <cstdint>

// GaussianIntegral2D — thread-per-pair compute + ASYNC BULK (TMA) store flush.
//
// Each thread owns one (b1,b2) pair: computes 49 rotated/translated points
// into its warp's smem tile (conflict-free STS.64) and accumulates the MVN
// integral in registers. The tile flush is ONE cp.async.bulk.global per warp
// (12544 B contiguous), drained by the TMA engine off the warp's critical
// path. Each warp processes ITERS tiles; inter-warp overlap hides the drain.

#define LOG2PI_F 1.8378770664093453f

static constexpr int Q        = 49;
static constexpr int TPB      = 512;
static constexpr int WARPS    = TPB / 32;            // 16
static constexpr int ITERS    = 2;                   // tiles per warp
static constexpr int TILE_F   = 32 * 2 * Q;          // 3136 floats = 12544 B
static constexpr int TILE_B   = TILE_F * 4;
static constexpr int QD_OFF_F = WARPS * TILE_F;
static constexpr size_t SMEM_BYTES = (size_t)QD_OFF_F * 4 + (size_t)Q * 16 + 16;

__device__ __forceinline__ void bulk_store(void* gdst, uint32_t ssrc, int bytes) {
    asm volatile(
        "cp.async.bulk.global.shared::cta.bulk_group [%0], [%1], %2;"
        :: "l"(gdst), "r"(ssrc), "r"(bytes) : "memory");
}

__global__ void __launch_bounds__(TPB)
gauss_integral_kernel(const float* __restrict__ means,   // [P,2]
                      const float* __restrict__ covars,  // [P,4]
                      const float* __restrict__ rots,    // [P,4]
                      const float* __restrict__ trans,   // [P,2]
                      const float* __restrict__ eta,     // [2,Q]
                      const float* __restrict__ wts,     // [Q]
                      float* __restrict__ out_pts,       // [P,Q,2]
                      float* __restrict__ out_int,       // [P]
                      int npair)
{
    extern __shared__ float sm[];
    float4* qd = reinterpret_cast<float4*>(sm + QD_OFF_F);

    const int tid  = threadIdx.x;
    const int lane = tid & 31;
    const int wid  = tid >> 5;

    // Stage quadrature table once per block: {ex, ey, w, 0} per point.
    if (tid < Q)
        qd[tid] = make_float4(eta[tid], eta[Q + tid], wts[tid], 0.0f);
    __syncthreads();

    float* buf = sm + wid * TILE_F;
    float2* row = reinterpret_cast<float2*>(buf) + lane * Q;
    const uint32_t sbuf = (uint32_t)__cvta_generic_to_shared(buf);

    #pragma unroll
    for (int k = 0; k < ITERS; ++k) {
        const int tile  = (blockIdx.x * WARPS + wid) * ITERS + k;
        const int pbase = tile * 32;
        const int p     = pbase + lane;

        // Make sure the TMA engine finished READING this buffer (prev iter).
        if (lane == 0)
            asm volatile("cp.async.bulk.wait_group.read 0;" ::: "memory");
        __syncwarp();

        if (p < npair) {
            // Coalesced per-lane parameter loads.
            const float2 m = reinterpret_cast<const float2*>(means)[p];
            const float4 c = reinterpret_cast<const float4*>(covars)[p];
            const float4 r = reinterpret_cast<const float4*>(rots)[p];
            const float2 t = reinterpret_cast<const float2*>(trans)[p];

            const float det  = c.x * c.w - c.y * c.z;
            const float kinv = -0.5f * __frcp_rn(det);
            const float base = fmaf(-0.5f, __logf(det), -LOG2PI_F);
            const float csum = c.y + c.z;

            float acc0 = 0.0f, acc1 = 0.0f;

            #pragma unroll 7
            for (int q = 0; q < Q; ++q) {
                const float4 e = qd[q];                       // broadcast LDS.128
                const float px = fmaf(r.x, e.x, fmaf(r.y, e.y, t.x));
                const float py = fmaf(r.z, e.x, fmaf(r.w, e.y, t.y));
                row[q] = make_float2(px, py);                 // STS.64, bank-clean
                const float dx = px - m.x, dy = py - m.y;
                const float quad = fmaf(c.w * dx, dx,
                                   fmaf(-csum * dx, dy, c.x * dy * dy));
                const float v = __expf(fmaf(kinv, quad, base)) * e.z;
                if (q & 1) acc1 += v; else acc0 += v;
            }

            out_int[p] = fminf(fmaxf(acc0 + acc1, 0.0f), 1.0f);
        }
        __syncwarp();

        const int rem = npair - pbase;
        if (rem >= 32) {
            if (lane == 0) {
                asm volatile("fence.proxy.async.shared::cta;" ::: "memory");
                bulk_store(out_pts + (size_t)pbase * (2 * Q), sbuf, TILE_B);
                asm volatile("cp.async.bulk.commit_group;" ::: "memory");
            }
        } else if (rem > 0) {
            // Tail tile (not hit for P = 524288): direct copy.
            const int nf = rem * 2 * Q;
            float* d = out_pts + (size_t)pbase * (2 * Q);
            for (int i = lane; i < nf; i += 32) d[i] = buf[i];
        }
        __syncwarp();
    }

    // Ensure all bulk stores fully complete before block teardown.
    if (lane == 0)
        asm volatile("cp.async.bulk.wait_group 0;" ::: "memory");
}

extern "C" void kernel_launch(void* const* d_in, const int* in_sizes, int n_in,
                              void* d_out, int out_size)
{
    const float* means  = (const float*)d_in[0];
    const float* covars = (const float*)d_in[1];
    const float* rots   = (const float*)d_in[2];
    const float* trans  = (const float*)d_in[3];
    const float* eta    = (const float*)d_in[4];
    const float* wts    = (const float*)d_in[5];

    const int npair = in_sizes[0] / 2;

    float* out_pts = (float*)d_out;
    float* out_int = out_pts + (size_t)npair * (size_t)(2 * Q);

    cudaFuncSetAttribute(gauss_integral_kernel,
                         cudaFuncAttributeMaxDynamicSharedMemorySize,
                         (int)SMEM_BYTES);

    const int pairs_per_block = WARPS * ITERS * 32;   // 1024
    const int blocks = (npair + pairs_per_block - 1) / pairs_per_block;
    gauss_integral_kernel<<<blocks, TPB, SMEM_BYTES>>>(
        means, covars, rots, trans, eta, wts, out_pts, out_int, npair);
}

// round 5
// speedup vs baseline: 1.2582x; 1.1258x over previous
#include <cuda_runtime.h>
#include <cstddef>

// GaussianIntegral2D — 8-lanes-per-pair, direct coalesced-ish stores, NO smem
// staging. Warp = 4 pairs; lane (8g+s) handles pair g, points q = s+8k.
// Per warp-iteration the stores form four contiguous 64B chunks (stride 392B)
// -> ~1.25x sector amplification, but zero staging traffic and register-
// limited occupancy (~3-4x more resident warps than the smem variants).
//
// exp folding: integrand = exp2( kinv2*quad + base2 + log2(w_q) ), with
// kinv2 = -0.5*log2e/det, base2 = -0.5*log2(det) - log2(2*pi*e^0)... i.e.
// all constants pre-folded; one FADD + FMA + EX2 per point tail.

#define LOG2PI_X_LOG2E_F 2.651496129472319f   // log2(2*pi)
#define NEG_HALF_LOG2E_F (-0.7213475204444817f)

static constexpr int Q   = 49;
static constexpr int TPB = 256;

__global__ void __launch_bounds__(TPB, 6)
gauss_integral_kernel(const float* __restrict__ means,   // [P,2]
                      const float* __restrict__ covars,  // [P,4]
                      const float* __restrict__ rots,    // [P,4]
                      const float* __restrict__ trans,   // [P,2]
                      const float* __restrict__ eta,     // [2,Q]
                      const float* __restrict__ wts,     // [Q]
                      float* __restrict__ out_pts,       // [P,Q,2]
                      float* __restrict__ out_int,       // [P]
                      int npair)
{
    __shared__ float4 qd[Q + 7];   // {ex, ey, log2(w), 0} per point (tiny)

    const int tid = threadIdx.x;
    if (tid < Q)
        qd[tid] = make_float4(eta[tid], eta[Q + tid], __log2f(wts[tid]), 0.0f);
    if (tid >= Q && tid < Q + 7)
        qd[tid] = make_float4(0.f, 0.f, 0.f, 0.f);   // pad: q=49..55 harmless
    __syncthreads();

    const int lane = tid & 31;
    const int s    = lane & 7;      // sub-lane within 8-lane group
    const int g    = lane >> 3;     // group (pair) index within warp

    // Pair handled by this thread's group.
    const int p = ((blockIdx.x * TPB + tid) >> 5) * 4 + g;
    if (p >= npair) return;

    // Params: 8 lanes per group load the same address (L1 broadcast).
    const float2 m = reinterpret_cast<const float2*>(means)[p];
    const float4 c = reinterpret_cast<const float4*>(covars)[p]; // c00 c01 c10 c11
    const float4 r = reinterpret_cast<const float4*>(rots)[p];
    const float2 t = reinterpret_cast<const float2*>(trans)[p];

    const float det   = c.x * c.w - c.y * c.z;
    const float kinv2 = NEG_HALF_LOG2E_F * __frcp_rn(det);        // -0.5*log2e/det
    const float base2 = fmaf(-0.5f, __log2f(det), -LOG2PI_X_LOG2E_F);
    const float csum  = c.y + c.z;

    float2* gp = reinterpret_cast<float2*>(out_pts) + (size_t)p * Q;

    float acc = 0.0f;

    #pragma unroll
    for (int k = 0; k < 7; ++k) {
        const int q = s + 8 * k;                 // lane s covers q = s, s+8, ...
        const bool live = (q < Q);               // only k=6, s>0 is dead
        const float4 e = qd[q];                  // LDS.128, conflict-free
        const float px = fmaf(r.x, e.x, fmaf(r.y, e.y, t.x));
        const float py = fmaf(r.z, e.x, fmaf(r.w, e.y, t.y));
        if (live) {
            __stcs(gp + q, make_float2(px, py)); // 4x 64B chunks per warp instr
            const float dx = px - m.x, dy = py - m.y;
            const float quad = fmaf(c.w * dx, dx,
                               fmaf(-csum * dx, dy, c.x * dy * dy));
            acc += exp2f(fmaf(kinv2, quad, base2 + e.z));
        }
    }

    // Reduce over the 8 lanes of this group.
    acc += __shfl_down_sync(0xffffffffu, acc, 4, 8);
    acc += __shfl_down_sync(0xffffffffu, acc, 2, 8);
    acc += __shfl_down_sync(0xffffffffu, acc, 1, 8);

    if (s == 0)
        out_int[p] = fminf(fmaxf(acc, 0.0f), 1.0f);  // lanes 0,8,16,24: 16B coalesced
}

extern "C" void kernel_launch(void* const* d_in, const int* in_sizes, int n_in,
                              void* d_out, int out_size)
{
    const float* means  = (const float*)d_in[0];
    const float* covars = (const float*)d_in[1];
    const float* rots   = (const float*)d_in[2];
    const float* trans  = (const float*)d_in[3];
    const float* eta    = (const float*)d_in[4];
    const float* wts    = (const float*)d_in[5];

    const int npair = in_sizes[0] / 2;

    float* out_pts = (float*)d_out;
    float* out_int = out_pts + (size_t)npair * (size_t)(2 * Q);

    // 4 pairs per warp, 8 warps per block -> 32 pairs per block.
    const int blocks = (npair + 31) / 32;
    gauss_integral_kernel<<<blocks, TPB>>>(
        means, covars, rots, trans, eta, wts, out_pts, out_int, npair);
}

// round 6
// speedup vs baseline: 1.2625x; 1.0034x over previous
#include <cuda_runtime.h>
#include <cstddef>

// GaussianIntegral2D — 8-lanes-per-pair, ALIGNED float4 stores + packed
// f32x2 arithmetic (Blackwell FFMA2), no smem staging of outputs.
//
// Pair stride is 392B = 8 + 24*16. Parity phase phi = p&1:
//   phi=0: 24 aligned float4 cover points 0..47, float2 tail = point 48 @+384
//   phi=1: float2 head = point 0 @+0, 24 aligned float4 cover points 1..48 @+8
// Lane (8g+s) of a warp owns pair g and float4 slots j = s+8k, k=0..2.
// Each float4 = two adjacent quadrature points -> math done 2-wide with
// fma.rn.f32x2 on packed register pairs (ptxas never auto-generates these).

#define LOG2_2PI_F 2.651496129472319f          // log2(2*pi)
#define NEG_HALF_LOG2E_F (-0.7213475204444817f) // -0.5 * log2(e)

static constexpr int Q   = 49;
static constexpr int TPB = 256;

typedef unsigned long long ull;

__device__ __forceinline__ ull pk2(float lo, float hi) {
    ull r; asm("mov.b64 %0,{%1,%2};" : "=l"(r) : "f"(lo), "f"(hi)); return r;
}
__device__ __forceinline__ void up2(ull v, float& lo, float& hi) {
    asm("mov.b64 {%0,%1},%2;" : "=f"(lo), "=f"(hi) : "l"(v));
}
__device__ __forceinline__ ull fma2_(ull a, ull b, ull c) {
    ull d; asm("fma.rn.f32x2 %0,%1,%2,%3;" : "=l"(d) : "l"(a), "l"(b), "l"(c)); return d;
}
__device__ __forceinline__ ull mul2_(ull a, ull b) {
    ull d; asm("mul.rn.f32x2 %0,%1,%2;" : "=l"(d) : "l"(a), "l"(b)); return d;
}
__device__ __forceinline__ ull add2_(ull a, ull b) {
    ull d; asm("add.rn.f32x2 %0,%1,%2;" : "=l"(d) : "l"(a), "l"(b)); return d;
}

__global__ void __launch_bounds__(TPB)
gauss_integral_kernel(const float* __restrict__ means,   // [P,2]
                      const float* __restrict__ covars,  // [P,4]
                      const float* __restrict__ rots,    // [P,4]
                      const float* __restrict__ trans,   // [P,2]
                      const float* __restrict__ eta,     // [2,Q]
                      const float* __restrict__ wts,     // [Q]
                      float* __restrict__ out_pts,       // [P,Q,2]
                      float* __restrict__ out_int,       // [P]
                      int npair)
{
    // Adjacent-point packed tables: entry u = points (u, min(u+1,48)).
    __shared__ float4 exy[Q];   // {ex[u], ex[u+1], ey[u], ey[u+1]}
    __shared__ float2 lw2[Q];   // {log2 w[u], log2 w[u+1]}

    const int tid = threadIdx.x;
    if (tid < Q) {
        const int u1 = (tid + 1 < Q) ? tid + 1 : Q - 1;
        exy[tid] = make_float4(eta[tid], eta[u1], eta[Q + tid], eta[Q + u1]);
        lw2[tid] = make_float2(__log2f(wts[tid]), __log2f(wts[u1]));
    }
    __syncthreads();

    const int lane = tid & 31;
    const int s    = lane & 7;      // float4 slot phase within group
    const int g    = lane >> 3;     // pair group within warp

    const int p = ((blockIdx.x * TPB + tid) >> 5) * 4 + g;
    if (p >= npair) return;         // group-uniform exit

    const int phi = p & 1;          // alignment parity of this pair's row

    // Per-pair params: 8 lanes/group load the same address (L1 broadcast).
    const float2 m = reinterpret_cast<const float2*>(means)[p];
    const float4 c = reinterpret_cast<const float4*>(covars)[p]; // c00 c01 c10 c11
    const float4 r = reinterpret_cast<const float4*>(rots)[p];
    const float2 t = reinterpret_cast<const float2*>(trans)[p];

    const float det   = c.x * c.w - c.y * c.z;
    const float kinv2 = NEG_HALF_LOG2E_F * __frcp_rn(det);
    const float base2 = fmaf(-0.5f, __log2f(det), -LOG2_2PI_F);
    const float csum  = c.y + c.z;

    // Packed per-pair constants (register pairs).
    const ull rx2 = pk2(r.x, r.x), ry2 = pk2(r.y, r.y);
    const ull rz2 = pk2(r.z, r.z), rw2 = pk2(r.w, r.w);
    const ull tx2 = pk2(t.x, t.x), ty2 = pk2(t.y, t.y);
    const ull nmx2 = pk2(-m.x, -m.x), nmy2 = pk2(-m.y, -m.y);
    const ull cw2 = pk2(c.w, c.w), cx2 = pk2(c.x, c.x);
    const ull ncs2 = pk2(-csum, -csum);
    const ull ki2 = pk2(kinv2, kinv2), bb2 = pk2(base2, base2);

    char* const outb = reinterpret_cast<char*>(out_pts) + (size_t)p * (size_t)(8 * Q);

    float acc0 = 0.0f, acc1 = 0.0f;

    #pragma unroll
    for (int k = 0; k < 3; ++k) {
        const int j = s + 8 * k;          // float4 slot 0..23
        const int u = 2 * j + phi;        // first point in this slot (<=47)
        const float4 e = exy[u];
        const float2 w = lw2[u];
        const ull exv = pk2(e.x, e.y);
        const ull eyv = pk2(e.z, e.w);

        const ull pxv = fma2_(rx2, exv, fma2_(ry2, eyv, tx2));
        const ull pyv = fma2_(rz2, exv, fma2_(rw2, eyv, ty2));

        float px0, px1, py0, py1;
        up2(pxv, px0, px1); up2(pyv, py0, py1);
        __stcs(reinterpret_cast<float4*>(outb + 8 * phi + 16 * j),
               make_float4(px0, py0, px1, py1));      // 16B-aligned STG.128

        const ull dxv = add2_(pxv, nmx2);
        const ull dyv = add2_(pyv, nmy2);
        const ull quad = fma2_(mul2_(cw2, dxv), dxv,
                         fma2_(mul2_(ncs2, dxv), dyv,
                               mul2_(mul2_(cx2, dyv), dyv)));
        const ull ev = fma2_(ki2, quad, add2_(bb2, pk2(w.x, w.y)));
        float e0, e1; up2(ev, e0, e1);
        acc0 += exp2f(e0);
        acc1 += exp2f(e1);
    }

    // Scalar tail point: q=0 for odd pairs, q=48 for even pairs.
    if (s == 0) {
        const int q = phi ? 0 : Q - 1;
        const float4 e = exy[q];          // .x = ex[q], .z = ey[q]
        const float lw = lw2[q].x;
        const float px = fmaf(r.x, e.x, fmaf(r.y, e.z, t.x));
        const float py = fmaf(r.z, e.x, fmaf(r.w, e.z, t.y));
        __stcs(reinterpret_cast<float2*>(outb + (phi ? 0 : 8 * (Q - 1))),
               make_float2(px, py));
        const float dx = px - m.x, dy = py - m.y;
        const float quad = fmaf(c.w * dx, dx,
                           fmaf(-csum * dx, dy, c.x * dy * dy));
        acc0 += exp2f(fmaf(kinv2, quad, base2 + lw));
    }

    // Reduce over the 8 lanes of this group (group-local mask).
    float acc = acc0 + acc1;
    const unsigned gmask = 0xFFu << (g * 8);
    acc += __shfl_down_sync(gmask, acc, 4, 8);
    acc += __shfl_down_sync(gmask, acc, 2, 8);
    acc += __shfl_down_sync(gmask, acc, 1, 8);

    if (s == 0)
        out_int[p] = fminf(fmaxf(acc, 0.0f), 1.0f);
}

extern "C" void kernel_launch(void* const* d_in, const int* in_sizes, int n_in,
                              void* d_out, int out_size)
{
    const float* means  = (const float*)d_in[0];
    const float* covars = (const float*)d_in[1];
    const float* rots   = (const float*)d_in[2];
    const float* trans  = (const float*)d_in[3];
    const float* eta    = (const float*)d_in[4];
    const float* wts    = (const float*)d_in[5];

    const int npair = in_sizes[0] / 2;

    float* out_pts = (float*)d_out;
    float* out_int = out_pts + (size_t)npair * (size_t)(2 * Q);

    // 4 pairs per warp, 8 warps per block -> 32 pairs per block.
    const int blocks = (npair + 31) / 32;
    gauss_integral_kernel<<<blocks, TPB>>>(
        means, covars, rots, trans, eta, wts, out_pts, out_int, npair);
}

// round 7
// speedup vs baseline: 1.3900x; 1.1010x over previous
#include <cuda_runtime.h>
#include <cstddef>

// GaussianIntegral2D — 8-lanes-per-pair, register-resident quadrature table,
// grid-stride over pair-quads with software-prefetched params. NO smem in the
// hot path, aligned STG.128 outputs.
//
// Warp = 4 groups of 8 lanes; group g of quad qid owns pair p = 4*qid + g.
// Since 4*qid is even, phi = p&1 = g&1 is FIXED per thread -> each thread's
// 6 quadrature points (u = 2*(s+8k)+phi, +pair point) are loop-invariant and
// live in registers. Inner loop: param LDGs (prefetched one iteration ahead),
// pure FMA/EX2 math, 3 aligned STG.128 per thread + small tails.

#define LOG2_2PI_F 2.651496129472319f           // log2(2*pi)
#define NEG_HALF_LOG2E_F (-0.7213475204444817f) // -0.5 * log2(e)

static constexpr int Q   = 49;
static constexpr int TPB = 256;

struct Params { float2 m, t; float4 c, r; };

__device__ __forceinline__ void load_params(
    const float* __restrict__ means, const float* __restrict__ covars,
    const float* __restrict__ rots,  const float* __restrict__ trans,
    int p, Params& P)
{
    P.m = reinterpret_cast<const float2*>(means)[p];
    P.c = reinterpret_cast<const float4*>(covars)[p];   // c00 c01 c10 c11
    P.r = reinterpret_cast<const float4*>(rots)[p];
    P.t = reinterpret_cast<const float2*>(trans)[p];
}

__global__ void __launch_bounds__(TPB)
gauss_integral_kernel(const float* __restrict__ means,   // [P,2]
                      const float* __restrict__ covars,  // [P,4]
                      const float* __restrict__ rots,    // [P,4]
                      const float* __restrict__ trans,   // [P,2]
                      const float* __restrict__ eta,     // [2,Q]
                      const float* __restrict__ wts,     // [Q]
                      float* __restrict__ out_pts,       // [P,Q,2]
                      float* __restrict__ out_int,       // [P]
                      int npair)
{
    const int tid  = threadIdx.x;
    const int lane = tid & 31;
    const int s    = lane & 7;       // slot phase within group
    const int g    = lane >> 3;      // group within warp
    const int phi  = g & 1;          // pair parity — FIXED per thread

    // Register-resident quadrature data: 6 points per thread (2 per slot).
    float ex[6], ey[6], lw[6];
    #pragma unroll
    for (int k = 0; k < 3; ++k) {
        const int u = 2 * (s + 8 * k) + phi;      // 0..47 (phi=0) / 1..48 (phi=1)
        ex[2*k]   = eta[u];     ey[2*k]   = eta[Q + u];
        ex[2*k+1] = eta[u + 1]; ey[2*k+1] = eta[Q + u + 1];
        lw[2*k]   = __log2f(wts[u]);
        lw[2*k+1] = __log2f(wts[u + 1]);
    }
    // Tail point (handled by s==0 lane): q=0 for phi=1, q=48 for phi=0.
    const int qt = phi ? 0 : Q - 1;
    const float ext = eta[qt], eyt = eta[Q + qt];
    const float lwt = __log2f(wts[qt]);

    const int warp_g = (blockIdx.x * TPB + tid) >> 5;
    const int nwarp  = (gridDim.x * TPB) >> 5;
    const int nquad  = (npair + 3) >> 2;

    int  qid   = warp_g;
    bool valid = (qid < nquad);
    int  p     = qid * 4 + g;
    Params P;
    if (valid && p < npair)
        load_params(means, covars, rots, trans, p, P);

    while (valid) {
        // ---- prefetch next iteration's params (hides DRAM latency) ----
        const int  qn     = qid + nwarp;
        const bool vnext  = (qn < nquad);
        const int  pn     = qn * 4 + g;
        Params Pn;
        if (vnext && pn < npair)
            load_params(means, covars, rots, trans, pn, Pn);

        // ---- compute current pair ----
        if (p < npair) {
            const float det   = P.c.x * P.c.w - P.c.y * P.c.z;
            const float kinv2 = NEG_HALF_LOG2E_F * __frcp_rn(det);
            const float base2 = fmaf(-0.5f, __log2f(det), -LOG2_2PI_F);
            const float csum  = P.c.y + P.c.z;

            char* const outb = reinterpret_cast<char*>(out_pts)
                             + (size_t)p * (size_t)(8 * Q);

            float acc0 = 0.0f, acc1 = 0.0f;

            #pragma unroll
            for (int k = 0; k < 3; ++k) {
                const int j = s + 8 * k;          // float4 slot 0..23
                const float px0 = fmaf(P.r.x, ex[2*k],   fmaf(P.r.y, ey[2*k],   P.t.x));
                const float py0 = fmaf(P.r.z, ex[2*k],   fmaf(P.r.w, ey[2*k],   P.t.y));
                const float px1 = fmaf(P.r.x, ex[2*k+1], fmaf(P.r.y, ey[2*k+1], P.t.x));
                const float py1 = fmaf(P.r.z, ex[2*k+1], fmaf(P.r.w, ey[2*k+1], P.t.y));

                __stcs(reinterpret_cast<float4*>(outb + 8 * phi + 16 * j),
                       make_float4(px0, py0, px1, py1));   // 16B-aligned STG.128

                float dx = px0 - P.m.x, dy = py0 - P.m.y;
                float quad = fmaf(P.c.w * dx, dx,
                             fmaf(-csum * dx, dy, P.c.x * dy * dy));
                acc0 += exp2f(fmaf(kinv2, quad, base2 + lw[2*k]));

                dx = px1 - P.m.x; dy = py1 - P.m.y;
                quad = fmaf(P.c.w * dx, dx,
                       fmaf(-csum * dx, dy, P.c.x * dy * dy));
                acc1 += exp2f(fmaf(kinv2, quad, base2 + lw[2*k+1]));
            }

            // Scalar tail point (one per pair).
            if (s == 0) {
                const float px = fmaf(P.r.x, ext, fmaf(P.r.y, eyt, P.t.x));
                const float py = fmaf(P.r.z, ext, fmaf(P.r.w, eyt, P.t.y));
                __stcs(reinterpret_cast<float2*>(outb + (phi ? 0 : 8 * (Q - 1))),
                       make_float2(px, py));
                const float dx = px - P.m.x, dy = py - P.m.y;
                const float quad = fmaf(P.c.w * dx, dx,
                                   fmaf(-csum * dx, dy, P.c.x * dy * dy));
                acc0 += exp2f(fmaf(kinv2, quad, base2 + lwt));
            }

            // Reduce over the 8 lanes of this group.
            float acc = acc0 + acc1;
            const unsigned gmask = 0xFFu << (g * 8);
            acc += __shfl_down_sync(gmask, acc, 4, 8);
            acc += __shfl_down_sync(gmask, acc, 2, 8);
            acc += __shfl_down_sync(gmask, acc, 1, 8);

            if (s == 0)
                out_int[p] = fminf(fmaxf(acc, 0.0f), 1.0f);  // 4 lanes -> 16B coalesced
        }

        P = Pn; qid = qn; p = pn; valid = vnext;
    }
}

extern "C" void kernel_launch(void* const* d_in, const int* in_sizes, int n_in,
                              void* d_out, int out_size)
{
    const float* means  = (const float*)d_in[0];
    const float* covars = (const float*)d_in[1];
    const float* rots   = (const float*)d_in[2];
    const float* trans  = (const float*)d_in[3];
    const float* eta    = (const float*)d_in[4];
    const float* wts    = (const float*)d_in[5];

    const int npair = in_sizes[0] / 2;

    float* out_pts = (float*)d_out;
    float* out_int = out_pts + (size_t)npair * (size_t)(2 * Q);

    // ~8 grid-stride iterations per warp at P = 524288.
    const int blocks = 2048;
    gauss_integral_kernel<<<blocks, TPB>>>(
        means, covars, rots, trans, eta, wts, out_pts, out_int, npair);
}